// round 16
// baseline (speedup 1.0000x reference)
#include <cuda_runtime.h>
#include <cuda_fp16.h>
#include <mma.h>
#include <math.h>

using namespace nvcuda;

#define N_NODES 50000
#define N_EDGES 1600000
#define E_TOT   (N_EDGES + N_NODES)
#define HID     128
#define IND     13
#define OUTD    5
#define SCAN_BS 512
#define NBLK    ((N_NODES + SCAN_BS - 1) / SCAN_BS)   // 98

// ---------------- scratch (static device globals; no allocation) ----------------
__device__ int      g_ssrc[E_TOT];           // CSR-sorted source indices (by dst)
__device__ int      g_rank[N_EDGES];         // rank of edge within its dst bucket
__device__ int      g_cnt[N_NODES];
__device__ int      g_off[N_NODES + 1];
__device__ unsigned g_maxas[3];              // per-layer global max of a_src·h (encoded)
__device__ __align__(16) __half g_hh[N_NODES * HID];    // transformed features, fp16
__device__ __align__(16) __half g_feath[N_NODES * HID]; // layer-1 output, fp16
__device__ __align__(16) __half g_W2h[HID * HID];       // W2 in fp16
__device__ float    g_as[N_NODES];
__device__ float    g_ad[N_NODES];
__device__ float    g_h5[N_NODES * OUTD];

// order-preserving float<->uint encoding (atomicMax-able, order-invariant => deterministic)
__device__ __forceinline__ unsigned enc_f(float f) {
    unsigned u = __float_as_uint(f);
    return (u >> 31) ? ~u : (u | 0x80000000u);
}
__device__ __forceinline__ float dec_f(unsigned e) {
    return __uint_as_float((e >> 31) ? (e ^ 0x80000000u) : ~e);
}
__device__ __forceinline__ float leaky(float e) { return e > 0.f ? e : 0.2f * e; }

// block-level (8 warps) max reduce then ONE atomic per block
__device__ __forceinline__ void block_atomic_max(unsigned* dst, float s1, int warp, int lane,
                                                 float* smax) {
    if (lane == 0) smax[warp] = s1;
    __syncthreads();
    if (threadIdx.x == 0) {
        float m = smax[0];
#pragma unroll
        for (int w = 1; w < 8; ++w) m = fmaxf(m, smax[w]);
        atomicMax(dst, enc_f(m));
    }
}

// ---------------- init: cnt=0 + W2->fp16 + maxas ----------
__global__ void k_init(const float* __restrict__ W2) {
    int i = blockIdx.x * blockDim.x + threadIdx.x;
    if (i < N_NODES) g_cnt[i] = 0;
    if (i < HID * HID) g_W2h[i] = __float2half(W2[i]);
    if (i < 3) g_maxas[i] = 0u;
}

// ---------------- CSR build ----------------
// hist: count per dst AND record each edge's bucket rank
__global__ void k_hist(const int* __restrict__ ei) {
    int e4 = blockIdx.x * blockDim.x + threadIdx.x;
    if (e4 >= N_EDGES / 4) return;
    int4 d = ((const int4*)(ei + N_EDGES))[e4];        // dst half (int32: JAX x64 disabled)
    int4 r;
    r.x = atomicAdd(&g_cnt[d.x], 1);
    r.y = atomicAdd(&g_cnt[d.y], 1);
    r.z = atomicAdd(&g_cnt[d.z], 1);
    r.w = atomicAdd(&g_cnt[d.w], 1);
    ((int4*)g_rank)[e4] = r;
}

// offsets: block prefix via strided sum (+1 per node for self-loop) + intra-block scan.
// Also places each node's self-loop at slot off[i] (bucket position 0).
__global__ void k_offsets() {
    __shared__ int sm[SCAN_BS];
    int t = threadIdx.x;
    int base = blockIdx.x * SCAN_BS;
    int pre = 0;
    for (int i = t; i < base; i += SCAN_BS) pre += g_cnt[i];
    sm[t] = pre;
    __syncthreads();
    for (int o = SCAN_BS / 2; o > 0; o >>= 1) {
        if (t < o) sm[t] += sm[t + o];
        __syncthreads();
    }
    int blockpre = sm[0] + base;            // +1 self-loop for each preceding node
    __syncthreads();
    int i = base + t;
    int v = (i < N_NODES) ? g_cnt[i] + 1 : 0;   // +1 = self-loop
    sm[t] = v;
    __syncthreads();
    for (int o = 1; o < SCAN_BS; o <<= 1) {
        int u = (t >= o) ? sm[t - o] : 0;
        __syncthreads();
        sm[t] += u;
        __syncthreads();
    }
    if (i < N_NODES) {
        int excl = sm[t] - v + blockpre;
        g_off[i] = excl;
        g_ssrc[excl] = i;                   // self-loop occupies bucket slot 0
        if (i == N_NODES - 1) g_off[N_NODES] = excl + v;   // == E_TOT
    }
}

// fill: atomic-free scatter — pos = off[dst] + 1 + rank
__global__ void k_fill(const int* __restrict__ ei) {
    int e4 = blockIdx.x * blockDim.x + threadIdx.x;
    if (e4 >= N_EDGES / 4) return;
    int4 s = ((const int4*)ei)[e4];
    int4 d = ((const int4*)(ei + N_EDGES))[e4];
    int4 r = ((const int4*)g_rank)[e4];
    g_ssrc[g_off[d.x] + 1 + r.x] = s.x;
    g_ssrc[g_off[d.y] + 1 + r.y] = s.y;
    g_ssrc[g_off[d.z] + 1 + r.z] = s.z;
    g_ssrc[g_off[d.w] + 1 + r.w] = s.w;
}

// ---------------- helpers ----------------
__device__ __forceinline__ uint2 pack_half4(float a, float b, float c, float d) {
    __half2 h0 = __float22half2_rn(make_float2(a, b));
    __half2 h1 = __float22half2_rn(make_float2(c, d));
    uint2 u;
    u.x = *reinterpret_cast<unsigned*>(&h0);
    u.y = *reinterpret_cast<unsigned*>(&h1);
    return u;
}
__device__ __forceinline__ float4 unpack_half4(uint2 u) {
    __half2 h0 = *reinterpret_cast<__half2*>(&u.x);
    __half2 h1 = *reinterpret_cast<__half2*>(&u.y);
    float2 f0 = __half22float2(h0), f1 = __half22float2(h1);
    return make_float4(f0.x, f0.y, f1.x, f1.y);
}

// ---------------- layer 1 GEMM (K=13) + fused attention dots + block-reduced max --
__global__ void k_gemm1(const float* __restrict__ x, const float* __restrict__ W1,
                        const float* __restrict__ a_src, const float* __restrict__ a_dst) {
    __shared__ __align__(16) float Ws[IND * HID];
    __shared__ __align__(16) float As[HID];
    __shared__ __align__(16) float Ad[HID];
    __shared__ float smax[8];
    for (int i = threadIdx.x; i < IND * HID; i += blockDim.x) Ws[i] = W1[i];
    for (int i = threadIdx.x; i < HID; i += blockDim.x) { As[i] = a_src[i]; Ad[i] = a_dst[i]; }
    __syncthreads();
    int warp = threadIdx.x >> 5, lane = threadIdx.x & 31;
    int node = blockIdx.x * 8 + warp;     // exact: 50000 = 6250*8
    float xv[IND];
#pragma unroll
    for (int k = 0; k < IND; ++k) xv[k] = x[node * IND + k];
    float4 acc = {0.f, 0.f, 0.f, 0.f};
#pragma unroll
    for (int k = 0; k < IND; ++k) {
        float4 w = *(const float4*)&Ws[k * HID + lane * 4];
        acc.x += xv[k] * w.x; acc.y += xv[k] * w.y;
        acc.z += xv[k] * w.z; acc.w += xv[k] * w.w;
    }
    ((uint2*)g_hh)[node * 32 + lane] = pack_half4(acc.x, acc.y, acc.z, acc.w);
    float4 a1 = *(const float4*)&As[lane * 4];
    float4 a2 = *(const float4*)&Ad[lane * 4];
    float s1 = acc.x * a1.x + acc.y * a1.y + acc.z * a1.z + acc.w * a1.w;
    float s2 = acc.x * a2.x + acc.y * a2.y + acc.z * a2.z + acc.w * a2.w;
#pragma unroll
    for (int o = 16; o; o >>= 1) {
        s1 += __shfl_xor_sync(0xffffffffu, s1, o);
        s2 += __shfl_xor_sync(0xffffffffu, s2, o);
    }
    if (lane == 0) { g_as[node] = s1; g_ad[node] = s2; }
    block_atomic_max(&g_maxas[0], s1, warp, lane, smax);
}

// ---------------- layer 2 GEMM via WMMA + fused attention dots -------------------
// block 256 (8 warps), 64 rows x 128 cols. Warp w: row-tile w>>1, col-tiles (w&1)*4..+3.
#define FS_LD 136
__global__ void k_gemm2_wmma(const float* __restrict__ a_src, const float* __restrict__ a_dst) {
    __shared__ __align__(16) __half Fs[64 * FS_LD];
    __shared__ __align__(16) float  Os[8 * 256];       // per-warp 16x16 staging
    __shared__ float Asm[HID], Adm[HID];
    __shared__ float s_as[64], s_ad[64];
    int rowBase = blockIdx.x * 64;
    int warp = threadIdx.x >> 5, lane = threadIdx.x & 31;
    if (threadIdx.x < HID) { Asm[threadIdx.x] = a_src[threadIdx.x]; Adm[threadIdx.x] = a_dst[threadIdx.x]; }
    if (threadIdx.x < 64) { s_as[threadIdx.x] = 0.f; s_ad[threadIdx.x] = 0.f; }
    for (int v = threadIdx.x * 8; v < 64 * HID; v += 256 * 8) {
        int r = v >> 7, c = v & 127;
        int gr = rowBase + r;
        uint4 d = (gr < N_NODES) ? *(const uint4*)&g_feath[gr * HID + c]
                                 : make_uint4(0u, 0u, 0u, 0u);
        *(uint4*)&Fs[r * FS_LD + c] = d;
    }
    __syncthreads();
    int rowTile = warp >> 1;
    int colTile0 = (warp & 1) * 4;
    wmma::fragment<wmma::accumulator, 16, 16, 16, float> acc[4];
#pragma unroll
    for (int t = 0; t < 4; ++t) wmma::fill_fragment(acc[t], 0.f);
    for (int k = 0; k < HID; k += 16) {
        wmma::fragment<wmma::matrix_a, 16, 16, 16, __half, wmma::row_major> a;
        wmma::load_matrix_sync(a, &Fs[rowTile * 16 * FS_LD + k], FS_LD);
#pragma unroll
        for (int t = 0; t < 4; ++t) {
            wmma::fragment<wmma::matrix_b, 16, 16, 16, __half, wmma::row_major> b;
            wmma::load_matrix_sync(b, &g_W2h[k * HID + (colTile0 + t) * 16], HID);
            wmma::mma_sync(acc[t], a, b, acc[t]);
        }
    }
    float* os = &Os[warp * 256];
#pragma unroll
    for (int t = 0; t < 4; ++t) {
        wmma::store_matrix_sync(os, acc[t], 16, wmma::mem_row_major);
        __syncwarp();
        int r = lane >> 1, c8 = (lane & 1) * 8;
        int gr = rowBase + rowTile * 16 + r;
        int gc = (colTile0 + t) * 16 + c8;
        const float* p = &os[r * 16 + c8];
        if (gr < N_NODES) {
            __half2* dst = (__half2*)&g_hh[gr * HID + gc];
#pragma unroll
            for (int q = 0; q < 4; ++q)
                dst[q] = __float22half2_rn(make_float2(p[2 * q], p[2 * q + 1]));
        }
        // fused attention-dot partials (8 cols each)
        float ps = 0.f, pd = 0.f;
#pragma unroll
        for (int q = 0; q < 8; ++q) { ps += p[q] * Asm[gc + q]; pd += p[q] * Adm[gc + q]; }
        atomicAdd(&s_as[rowTile * 16 + r], ps);
        atomicAdd(&s_ad[rowTile * 16 + r], pd);
        __syncwarp();
    }
    __syncthreads();
    if (warp == 0) {
        float m = -1e30f;
#pragma unroll
        for (int it = 0; it < 2; ++it) {
            int rr = it * 32 + lane;
            int gr = rowBase + rr;
            if (gr < N_NODES) {
                float s1 = s_as[rr];
                g_as[gr] = s1;
                g_ad[gr] = s_ad[rr];
                m = fmaxf(m, s1);
            }
        }
#pragma unroll
        for (int o = 16; o; o >>= 1) m = fmaxf(m, __shfl_xor_sync(0xffffffffu, m, o));
        if (lane == 0) atomicMax(&g_maxas[1], enc_f(m));
    }
}

// ---------------- layer-1 softmax-aggregation, F=128 (warp per node, fp16 gather) --
// single edge pass: shift = leaky(global_max(as) + ad_i) >= all e_ij (softmax invariant)
__global__ void k_agg128(const float* __restrict__ b) {
    int warp = threadIdx.x >> 5, lane = threadIdx.x & 31;
    int i = blockIdx.x * 8 + warp;        // exact grid
    int start = g_off[i], end = g_off[i + 1];
    float adi = g_ad[i];
    float m = leaky(dec_f(g_maxas[0]) + adi);
    float4 acc = {0.f, 0.f, 0.f, 0.f};
    float denom = 0.f;
    const uint2* hh = (const uint2*)g_hh;
    int j = start;
    for (; j + 4 <= end; j += 4) {
        int s0 = g_ssrc[j], s1 = g_ssrc[j + 1], s2 = g_ssrc[j + 2], s3 = g_ssrc[j + 3];
        float e0 = g_as[s0] + adi, e1 = g_as[s1] + adi,
              e2 = g_as[s2] + adi, e3 = g_as[s3] + adi;
        uint2 p0 = hh[s0 * 32 + lane], p1 = hh[s1 * 32 + lane],
              p2 = hh[s2 * 32 + lane], p3 = hh[s3 * 32 + lane];
        float x0 = __expf(leaky(e0) - m), x1 = __expf(leaky(e1) - m),
              x2 = __expf(leaky(e2) - m), x3 = __expf(leaky(e3) - m);
        denom += (x0 + x1) + (x2 + x3);
        float4 h0 = unpack_half4(p0), h1 = unpack_half4(p1),
               h2 = unpack_half4(p2), h3 = unpack_half4(p3);
        acc.x += x0 * h0.x + x1 * h1.x + x2 * h2.x + x3 * h3.x;
        acc.y += x0 * h0.y + x1 * h1.y + x2 * h2.y + x3 * h3.y;
        acc.z += x0 * h0.z + x1 * h1.z + x2 * h2.z + x3 * h3.z;
        acc.w += x0 * h0.w + x1 * h1.w + x2 * h2.w + x3 * h3.w;
    }
    for (; j < end; ++j) {
        int s = g_ssrc[j];
        float ex = __expf(leaky(g_as[s] + adi) - m);
        denom += ex;
        float4 hv = unpack_half4(hh[s * 32 + lane]);
        acc.x += ex * hv.x; acc.y += ex * hv.y;
        acc.z += ex * hv.z; acc.w += ex * hv.w;
    }
    float inv = 1.f / (denom + 1e-16f);
    float4 bv = ((const float4*)b)[lane];
    float4 r;
    r.x = fmaxf(acc.x * inv + bv.x, 0.f); r.y = fmaxf(acc.y * inv + bv.y, 0.f);
    r.z = fmaxf(acc.z * inv + bv.z, 0.f); r.w = fmaxf(acc.w * inv + bv.w, 0.f);
    ((uint2*)g_feath)[i * 32 + lane] = pack_half4(r.x, r.y, r.z, r.w);
}

// ---------------- layer-2 aggregation + FUSED layer-3 GEMM (128->5) + dots + max ---
// Identical edge loop, but epilogue projects the finished row through W3 in-register:
// no feath write, no gemm3 kernel, no 12.8MB re-read.
__global__ void k_agg128_fin(const float* __restrict__ b,
                             const float* __restrict__ W3,
                             const float* __restrict__ a_src, const float* __restrict__ a_dst) {
    __shared__ float Ws[HID * OUTD];
    __shared__ float As[OUTD], Ad[OUTD];
    __shared__ float smax[8];
    for (int i = threadIdx.x; i < HID * OUTD; i += blockDim.x) Ws[i] = W3[i];
    if (threadIdx.x < OUTD) { As[threadIdx.x] = a_src[threadIdx.x]; Ad[threadIdx.x] = a_dst[threadIdx.x]; }
    __syncthreads();
    int warp = threadIdx.x >> 5, lane = threadIdx.x & 31;
    int i = blockIdx.x * 8 + warp;        // exact grid
    int start = g_off[i], end = g_off[i + 1];
    float adi = g_ad[i];
    float m = leaky(dec_f(g_maxas[1]) + adi);
    float4 acc = {0.f, 0.f, 0.f, 0.f};
    float denom = 0.f;
    const uint2* hh = (const uint2*)g_hh;
    int j = start;
    for (; j + 4 <= end; j += 4) {
        int s0 = g_ssrc[j], s1 = g_ssrc[j + 1], s2 = g_ssrc[j + 2], s3 = g_ssrc[j + 3];
        float e0 = g_as[s0] + adi, e1 = g_as[s1] + adi,
              e2 = g_as[s2] + adi, e3 = g_as[s3] + adi;
        uint2 p0 = hh[s0 * 32 + lane], p1 = hh[s1 * 32 + lane],
              p2 = hh[s2 * 32 + lane], p3 = hh[s3 * 32 + lane];
        float x0 = __expf(leaky(e0) - m), x1 = __expf(leaky(e1) - m),
              x2 = __expf(leaky(e2) - m), x3 = __expf(leaky(e3) - m);
        denom += (x0 + x1) + (x2 + x3);
        float4 h0 = unpack_half4(p0), h1 = unpack_half4(p1),
               h2 = unpack_half4(p2), h3 = unpack_half4(p3);
        acc.x += x0 * h0.x + x1 * h1.x + x2 * h2.x + x3 * h3.x;
        acc.y += x0 * h0.y + x1 * h1.y + x2 * h2.y + x3 * h3.y;
        acc.z += x0 * h0.z + x1 * h1.z + x2 * h2.z + x3 * h3.z;
        acc.w += x0 * h0.w + x1 * h1.w + x2 * h2.w + x3 * h3.w;
    }
    for (; j < end; ++j) {
        int s = g_ssrc[j];
        float ex = __expf(leaky(g_as[s] + adi) - m);
        denom += ex;
        float4 hv = unpack_half4(hh[s * 32 + lane]);
        acc.x += ex * hv.x; acc.y += ex * hv.y;
        acc.z += ex * hv.z; acc.w += ex * hv.w;
    }
    float inv = 1.f / (denom + 1e-16f);
    float4 bv = ((const float4*)b)[lane];
    float4 r;
    r.x = fmaxf(acc.x * inv + bv.x, 0.f); r.y = fmaxf(acc.y * inv + bv.y, 0.f);
    r.z = fmaxf(acc.z * inv + bv.z, 0.f); r.w = fmaxf(acc.w * inv + bv.w, 0.f);
    // fused layer-3 projection: hc[c] = sum_k r[k] * W3[k][c], warp-reduced
    int k0 = lane * 4;
    float hc[OUTD];
#pragma unroll
    for (int c = 0; c < OUTD; ++c) {
        float s = r.x * Ws[(k0 + 0) * OUTD + c] + r.y * Ws[(k0 + 1) * OUTD + c]
                + r.z * Ws[(k0 + 2) * OUTD + c] + r.w * Ws[(k0 + 3) * OUTD + c];
#pragma unroll
        for (int o = 16; o; o >>= 1) s += __shfl_xor_sync(0xffffffffu, s, o);
        hc[c] = s;
    }
    float s1 = 0.f;
    if (lane == 0) {
        float s2 = 0.f;
#pragma unroll
        for (int c = 0; c < OUTD; ++c) {
            g_h5[i * OUTD + c] = hc[c];
            s1 += hc[c] * As[c];
            s2 += hc[c] * Ad[c];
        }
        g_as[i] = s1; g_ad[i] = s2;
    }
    block_atomic_max(&g_maxas[2], s1, warp, lane, smax);
}

// ---------------- fused aggregation F=5 + bias + log_softmax (warp per node) -------
__global__ void k_agg5(const float* __restrict__ b3, float* __restrict__ out) {
    int warp = threadIdx.x >> 5, lane = threadIdx.x & 31;
    int i = blockIdx.x * 8 + warp;        // exact grid
    int start = g_off[i], end = g_off[i + 1];
    float adi = g_ad[i];
    float m = leaky(dec_f(g_maxas[2]) + adi);
    float a0 = 0.f, a1 = 0.f, a2 = 0.f, a3 = 0.f, a4 = 0.f, denom = 0.f;
    for (int j = start + lane; j < end; j += 32) {
        int s = g_ssrc[j];
        float ex = __expf(leaky(g_as[s] + adi) - m);
        denom += ex;
        const float* hp = &g_h5[s * OUTD];
        a0 += ex * hp[0]; a1 += ex * hp[1]; a2 += ex * hp[2];
        a3 += ex * hp[3]; a4 += ex * hp[4];
    }
#pragma unroll
    for (int o = 16; o; o >>= 1) {
        denom += __shfl_xor_sync(0xffffffffu, denom, o);
        a0 += __shfl_xor_sync(0xffffffffu, a0, o);
        a1 += __shfl_xor_sync(0xffffffffu, a1, o);
        a2 += __shfl_xor_sync(0xffffffffu, a2, o);
        a3 += __shfl_xor_sync(0xffffffffu, a3, o);
        a4 += __shfl_xor_sync(0xffffffffu, a4, o);
    }
    if (lane == 0) {
        float inv = 1.f / (denom + 1e-16f);
        float v[OUTD] = {a0 * inv + b3[0], a1 * inv + b3[1], a2 * inv + b3[2],
                         a3 * inv + b3[3], a4 * inv + b3[4]};
        float mx = -1e30f;
#pragma unroll
        for (int c = 0; c < OUTD; ++c) mx = fmaxf(mx, v[c]);
        float se = 0.f;
#pragma unroll
        for (int c = 0; c < OUTD; ++c) se += __expf(v[c] - mx);
        float lse = mx + logf(se);
#pragma unroll
        for (int c = 0; c < OUTD; ++c) out[i * OUTD + c] = v[c] - lse;
    }
}

// ---------------- launch ----------------
extern "C" void kernel_launch(void* const* d_in, const int* in_sizes, int n_in,
                              void* d_out, int out_size) {
    const float* x   = (const float*)d_in[0];
    const int*   ei  = (const int*)d_in[1];       // int32: JAX x64 is disabled
    const float* W1  = (const float*)d_in[2];
    const float* as1 = (const float*)d_in[3];
    const float* ad1 = (const float*)d_in[4];
    const float* b1  = (const float*)d_in[5];
    const float* W2  = (const float*)d_in[6];
    const float* as2 = (const float*)d_in[7];
    const float* ad2 = (const float*)d_in[8];
    const float* b2  = (const float*)d_in[9];
    const float* W3  = (const float*)d_in[10];
    const float* as3 = (const float*)d_in[11];
    const float* ad3 = (const float*)d_in[12];
    const float* b3  = (const float*)d_in[13];
    float* out = (float*)d_out;

    // CSR build (rebuilt every call — no caching)
    k_init<<<(N_NODES + 255) / 256, 256>>>(W2);
    k_hist<<<(N_EDGES / 4 + 255) / 256, 256>>>(ei);
    k_offsets<<<NBLK, SCAN_BS>>>();
    k_fill<<<(N_EDGES / 4 + 255) / 256, 256>>>(ei);

    int nwb = N_NODES / 8;   // 6250, exact — warp-per-node grids

    // layer 1
    k_gemm1<<<nwb, 256>>>(x, W1, as1, ad1);
    k_agg128<<<nwb, 256>>>(b1);
    // layer 2 (rowdot fused into GEMM epilogue)
    k_gemm2_wmma<<<(N_NODES + 63) / 64, 256>>>(as2, ad2);
    // layer-2 aggregation with fused layer-3 GEMM + dots + max
    k_agg128_fin<<<nwb, 256>>>(b2, W3, as3, ad3);
    // layer 3 softmax-aggregate + log_softmax
    k_agg5<<<nwb, 256>>>(b3, out);
}

// round 17
// speedup vs baseline: 1.0004x; 1.0004x over previous
#include <cuda_runtime.h>
#include <cuda_fp16.h>
#include <mma.h>
#include <math.h>

using namespace nvcuda;

#define N_NODES 50000
#define N_EDGES 1600000
#define E_TOT   (N_EDGES + N_NODES)
#define HID     128
#define IND     13
#define OUTD    5
#define SCAN_BS 512
#define NBLK    ((N_NODES + SCAN_BS - 1) / SCAN_BS)   // 98

// ---------------- scratch (static device globals; no allocation) ----------------
__device__ int      g_ssrc[E_TOT];           // CSR-sorted source indices (by dst)
__device__ int      g_rank[N_EDGES];         // rank of edge within its dst bucket
__device__ int      g_cnt[N_NODES];
__device__ int      g_off[N_NODES + 1];
__device__ unsigned g_maxas[2];              // layer-1/2 global max of a_src·h (encoded)
__device__ unsigned g_max2[32];              // layer-3 max, 32 spread slots (no block barrier)
__device__ __align__(16) __half g_hh[N_NODES * HID];    // transformed features, fp16
__device__ __align__(16) __half g_feath[N_NODES * HID]; // layer-1 output, fp16
__device__ __align__(16) __half g_W2h[HID * HID];       // W2 in fp16
__device__ float    g_as[N_NODES];
__device__ float    g_ad[N_NODES];
__device__ float    g_h5[N_NODES * OUTD];

// order-preserving float<->uint encoding (atomicMax-able, order-invariant => deterministic)
__device__ __forceinline__ unsigned enc_f(float f) {
    unsigned u = __float_as_uint(f);
    return (u >> 31) ? ~u : (u | 0x80000000u);
}
__device__ __forceinline__ float dec_f(unsigned e) {
    return __uint_as_float((e >> 31) ? (e ^ 0x80000000u) : ~e);
}
__device__ __forceinline__ float leaky(float e) { return e > 0.f ? e : 0.2f * e; }

// block-level (8 warps) max reduce then ONE atomic per block (uniform-work kernels only)
__device__ __forceinline__ void block_atomic_max(unsigned* dst, float s1, int warp, int lane,
                                                 float* smax) {
    if (lane == 0) smax[warp] = s1;
    __syncthreads();
    if (threadIdx.x == 0) {
        float m = smax[0];
#pragma unroll
        for (int w = 1; w < 8; ++w) m = fmaxf(m, smax[w]);
        atomicMax(dst, enc_f(m));
    }
}

// ---------------- init: cnt=0 + W2->fp16 + max accumulators ----------
__global__ void k_init(const float* __restrict__ W2) {
    int i = blockIdx.x * blockDim.x + threadIdx.x;
    if (i < N_NODES) g_cnt[i] = 0;
    if (i < HID * HID) g_W2h[i] = __float2half(W2[i]);
    if (i < 2) g_maxas[i] = 0u;
    if (i < 32) g_max2[i] = 0u;
}

// ---------------- CSR build ----------------
// hist: count per dst AND record each edge's bucket rank
__global__ void k_hist(const int* __restrict__ ei) {
    int e4 = blockIdx.x * blockDim.x + threadIdx.x;
    if (e4 >= N_EDGES / 4) return;
    int4 d = ((const int4*)(ei + N_EDGES))[e4];        // dst half (int32: JAX x64 disabled)
    int4 r;
    r.x = atomicAdd(&g_cnt[d.x], 1);
    r.y = atomicAdd(&g_cnt[d.y], 1);
    r.z = atomicAdd(&g_cnt[d.z], 1);
    r.w = atomicAdd(&g_cnt[d.w], 1);
    ((int4*)g_rank)[e4] = r;
}

// offsets: block prefix via strided sum (+1 per node for self-loop) + intra-block scan.
// Also places each node's self-loop at slot off[i] (bucket position 0).
__global__ void k_offsets() {
    __shared__ int sm[SCAN_BS];
    int t = threadIdx.x;
    int base = blockIdx.x * SCAN_BS;
    int pre = 0;
    for (int i = t; i < base; i += SCAN_BS) pre += g_cnt[i];
    sm[t] = pre;
    __syncthreads();
    for (int o = SCAN_BS / 2; o > 0; o >>= 1) {
        if (t < o) sm[t] += sm[t + o];
        __syncthreads();
    }
    int blockpre = sm[0] + base;            // +1 self-loop for each preceding node
    __syncthreads();
    int i = base + t;
    int v = (i < N_NODES) ? g_cnt[i] + 1 : 0;   // +1 = self-loop
    sm[t] = v;
    __syncthreads();
    for (int o = 1; o < SCAN_BS; o <<= 1) {
        int u = (t >= o) ? sm[t - o] : 0;
        __syncthreads();
        sm[t] += u;
        __syncthreads();
    }
    if (i < N_NODES) {
        int excl = sm[t] - v + blockpre;
        g_off[i] = excl;
        g_ssrc[excl] = i;                   // self-loop occupies bucket slot 0
        if (i == N_NODES - 1) g_off[N_NODES] = excl + v;   // == E_TOT
    }
}

// fill: atomic-free scatter — pos = off[dst] + 1 + rank
__global__ void k_fill(const int* __restrict__ ei) {
    int e4 = blockIdx.x * blockDim.x + threadIdx.x;
    if (e4 >= N_EDGES / 4) return;
    int4 s = ((const int4*)ei)[e4];
    int4 d = ((const int4*)(ei + N_EDGES))[e4];
    int4 r = ((const int4*)g_rank)[e4];
    g_ssrc[g_off[d.x] + 1 + r.x] = s.x;
    g_ssrc[g_off[d.y] + 1 + r.y] = s.y;
    g_ssrc[g_off[d.z] + 1 + r.z] = s.z;
    g_ssrc[g_off[d.w] + 1 + r.w] = s.w;
}

// ---------------- helpers ----------------
__device__ __forceinline__ uint2 pack_half4(float a, float b, float c, float d) {
    __half2 h0 = __float22half2_rn(make_float2(a, b));
    __half2 h1 = __float22half2_rn(make_float2(c, d));
    uint2 u;
    u.x = *reinterpret_cast<unsigned*>(&h0);
    u.y = *reinterpret_cast<unsigned*>(&h1);
    return u;
}
__device__ __forceinline__ float4 unpack_half4(uint2 u) {
    __half2 h0 = *reinterpret_cast<__half2*>(&u.x);
    __half2 h1 = *reinterpret_cast<__half2*>(&u.y);
    float2 f0 = __half22float2(h0), f1 = __half22float2(h1);
    return make_float4(f0.x, f0.y, f1.x, f1.y);
}

// ---------------- layer 1 GEMM (K=13) + fused attention dots + block-reduced max --
__global__ void k_gemm1(const float* __restrict__ x, const float* __restrict__ W1,
                        const float* __restrict__ a_src, const float* __restrict__ a_dst) {
    __shared__ __align__(16) float Ws[IND * HID];
    __shared__ __align__(16) float As[HID];
    __shared__ __align__(16) float Ad[HID];
    __shared__ float smax[8];
    for (int i = threadIdx.x; i < IND * HID; i += blockDim.x) Ws[i] = W1[i];
    for (int i = threadIdx.x; i < HID; i += blockDim.x) { As[i] = a_src[i]; Ad[i] = a_dst[i]; }
    __syncthreads();
    int warp = threadIdx.x >> 5, lane = threadIdx.x & 31;
    int node = blockIdx.x * 8 + warp;     // exact: 50000 = 6250*8
    float xv[IND];
#pragma unroll
    for (int k = 0; k < IND; ++k) xv[k] = x[node * IND + k];
    float4 acc = {0.f, 0.f, 0.f, 0.f};
#pragma unroll
    for (int k = 0; k < IND; ++k) {
        float4 w = *(const float4*)&Ws[k * HID + lane * 4];
        acc.x += xv[k] * w.x; acc.y += xv[k] * w.y;
        acc.z += xv[k] * w.z; acc.w += xv[k] * w.w;
    }
    ((uint2*)g_hh)[node * 32 + lane] = pack_half4(acc.x, acc.y, acc.z, acc.w);
    float4 a1 = *(const float4*)&As[lane * 4];
    float4 a2 = *(const float4*)&Ad[lane * 4];
    float s1 = acc.x * a1.x + acc.y * a1.y + acc.z * a1.z + acc.w * a1.w;
    float s2 = acc.x * a2.x + acc.y * a2.y + acc.z * a2.z + acc.w * a2.w;
#pragma unroll
    for (int o = 16; o; o >>= 1) {
        s1 += __shfl_xor_sync(0xffffffffu, s1, o);
        s2 += __shfl_xor_sync(0xffffffffu, s2, o);
    }
    if (lane == 0) { g_as[node] = s1; g_ad[node] = s2; }
    block_atomic_max(&g_maxas[0], s1, warp, lane, smax);
}

// ---------------- layer 2 GEMM via WMMA + fused attention dots -------------------
// block 256 (8 warps), 64 rows x 128 cols. Warp w: row-tile w>>1, col-tiles (w&1)*4..+3.
#define FS_LD 136
__global__ void k_gemm2_wmma(const float* __restrict__ a_src, const float* __restrict__ a_dst) {
    __shared__ __align__(16) __half Fs[64 * FS_LD];
    __shared__ __align__(16) float  Os[8 * 256];       // per-warp 16x16 staging
    __shared__ float Asm[HID], Adm[HID];
    __shared__ float s_as[64], s_ad[64];
    int rowBase = blockIdx.x * 64;
    int warp = threadIdx.x >> 5, lane = threadIdx.x & 31;
    if (threadIdx.x < HID) { Asm[threadIdx.x] = a_src[threadIdx.x]; Adm[threadIdx.x] = a_dst[threadIdx.x]; }
    if (threadIdx.x < 64) { s_as[threadIdx.x] = 0.f; s_ad[threadIdx.x] = 0.f; }
    for (int v = threadIdx.x * 8; v < 64 * HID; v += 256 * 8) {
        int r = v >> 7, c = v & 127;
        int gr = rowBase + r;
        uint4 d = (gr < N_NODES) ? *(const uint4*)&g_feath[gr * HID + c]
                                 : make_uint4(0u, 0u, 0u, 0u);
        *(uint4*)&Fs[r * FS_LD + c] = d;
    }
    __syncthreads();
    int rowTile = warp >> 1;
    int colTile0 = (warp & 1) * 4;
    wmma::fragment<wmma::accumulator, 16, 16, 16, float> acc[4];
#pragma unroll
    for (int t = 0; t < 4; ++t) wmma::fill_fragment(acc[t], 0.f);
    for (int k = 0; k < HID; k += 16) {
        wmma::fragment<wmma::matrix_a, 16, 16, 16, __half, wmma::row_major> a;
        wmma::load_matrix_sync(a, &Fs[rowTile * 16 * FS_LD + k], FS_LD);
#pragma unroll
        for (int t = 0; t < 4; ++t) {
            wmma::fragment<wmma::matrix_b, 16, 16, 16, __half, wmma::row_major> b;
            wmma::load_matrix_sync(b, &g_W2h[k * HID + (colTile0 + t) * 16], HID);
            wmma::mma_sync(acc[t], a, b, acc[t]);
        }
    }
    float* os = &Os[warp * 256];
#pragma unroll
    for (int t = 0; t < 4; ++t) {
        wmma::store_matrix_sync(os, acc[t], 16, wmma::mem_row_major);
        __syncwarp();
        int r = lane >> 1, c8 = (lane & 1) * 8;
        int gr = rowBase + rowTile * 16 + r;
        int gc = (colTile0 + t) * 16 + c8;
        const float* p = &os[r * 16 + c8];
        if (gr < N_NODES) {
            __half2* dst = (__half2*)&g_hh[gr * HID + gc];
#pragma unroll
            for (int q = 0; q < 4; ++q)
                dst[q] = __float22half2_rn(make_float2(p[2 * q], p[2 * q + 1]));
        }
        // fused attention-dot partials (8 cols each)
        float ps = 0.f, pd = 0.f;
#pragma unroll
        for (int q = 0; q < 8; ++q) { ps += p[q] * Asm[gc + q]; pd += p[q] * Adm[gc + q]; }
        atomicAdd(&s_as[rowTile * 16 + r], ps);
        atomicAdd(&s_ad[rowTile * 16 + r], pd);
        __syncwarp();
    }
    __syncthreads();
    if (warp == 0) {
        float m = -1e30f;
#pragma unroll
        for (int it = 0; it < 2; ++it) {
            int rr = it * 32 + lane;
            int gr = rowBase + rr;
            if (gr < N_NODES) {
                float s1 = s_as[rr];
                g_as[gr] = s1;
                g_ad[gr] = s_ad[rr];
                m = fmaxf(m, s1);
            }
        }
#pragma unroll
        for (int o = 16; o; o >>= 1) m = fmaxf(m, __shfl_xor_sync(0xffffffffu, m, o));
        if (lane == 0) atomicMax(&g_maxas[1], enc_f(m));
    }
}

// ---------------- layer-1 softmax-aggregation, F=128 (warp per node, fp16 gather) --
// single edge pass: shift = leaky(global_max(as) + ad_i) >= all e_ij (softmax invariant)
__global__ void k_agg128(const float* __restrict__ b) {
    int warp = threadIdx.x >> 5, lane = threadIdx.x & 31;
    int i = blockIdx.x * 8 + warp;        // exact grid
    int start = g_off[i], end = g_off[i + 1];
    float adi = g_ad[i];
    float m = leaky(dec_f(g_maxas[0]) + adi);
    float4 acc = {0.f, 0.f, 0.f, 0.f};
    float denom = 0.f;
    const uint2* hh = (const uint2*)g_hh;
    int j = start;
    for (; j + 4 <= end; j += 4) {
        int s0 = g_ssrc[j], s1 = g_ssrc[j + 1], s2 = g_ssrc[j + 2], s3 = g_ssrc[j + 3];
        float e0 = g_as[s0] + adi, e1 = g_as[s1] + adi,
              e2 = g_as[s2] + adi, e3 = g_as[s3] + adi;
        uint2 p0 = hh[s0 * 32 + lane], p1 = hh[s1 * 32 + lane],
              p2 = hh[s2 * 32 + lane], p3 = hh[s3 * 32 + lane];
        float x0 = __expf(leaky(e0) - m), x1 = __expf(leaky(e1) - m),
              x2 = __expf(leaky(e2) - m), x3 = __expf(leaky(e3) - m);
        denom += (x0 + x1) + (x2 + x3);
        float4 h0 = unpack_half4(p0), h1 = unpack_half4(p1),
               h2 = unpack_half4(p2), h3 = unpack_half4(p3);
        acc.x += x0 * h0.x + x1 * h1.x + x2 * h2.x + x3 * h3.x;
        acc.y += x0 * h0.y + x1 * h1.y + x2 * h2.y + x3 * h3.y;
        acc.z += x0 * h0.z + x1 * h1.z + x2 * h2.z + x3 * h3.z;
        acc.w += x0 * h0.w + x1 * h1.w + x2 * h2.w + x3 * h3.w;
    }
    for (; j < end; ++j) {
        int s = g_ssrc[j];
        float ex = __expf(leaky(g_as[s] + adi) - m);
        denom += ex;
        float4 hv = unpack_half4(hh[s * 32 + lane]);
        acc.x += ex * hv.x; acc.y += ex * hv.y;
        acc.z += ex * hv.z; acc.w += ex * hv.w;
    }
    float inv = 1.f / (denom + 1e-16f);
    float4 bv = ((const float4*)b)[lane];
    float4 r;
    r.x = fmaxf(acc.x * inv + bv.x, 0.f); r.y = fmaxf(acc.y * inv + bv.y, 0.f);
    r.z = fmaxf(acc.z * inv + bv.z, 0.f); r.w = fmaxf(acc.w * inv + bv.w, 0.f);
    ((uint2*)g_feath)[i * 32 + lane] = pack_half4(r.x, r.y, r.z, r.w);
}

// ---------------- layer-2 aggregation + FUSED layer-3 GEMM (128->5) + dots ---------
// NO post-loop block barrier: layer-3 max goes to 32 spread slots, one atomic per
// warp from lane 0 — warps exit independently (no degree-imbalance tail).
__global__ void k_agg128_fin(const float* __restrict__ b,
                             const float* __restrict__ W3,
                             const float* __restrict__ a_src, const float* __restrict__ a_dst) {
    __shared__ float Ws[HID * OUTD];
    __shared__ float As[OUTD], Ad[OUTD];
    for (int i = threadIdx.x; i < HID * OUTD; i += blockDim.x) Ws[i] = W3[i];
    if (threadIdx.x < OUTD) { As[threadIdx.x] = a_src[threadIdx.x]; Ad[threadIdx.x] = a_dst[threadIdx.x]; }
    __syncthreads();                      // uniform point, before divergent edge loops
    int warp = threadIdx.x >> 5, lane = threadIdx.x & 31;
    int i = blockIdx.x * 8 + warp;        // exact grid
    int start = g_off[i], end = g_off[i + 1];
    float adi = g_ad[i];
    float m = leaky(dec_f(g_maxas[1]) + adi);
    float4 acc = {0.f, 0.f, 0.f, 0.f};
    float denom = 0.f;
    const uint2* hh = (const uint2*)g_hh;
    int j = start;
    for (; j + 4 <= end; j += 4) {
        int s0 = g_ssrc[j], s1 = g_ssrc[j + 1], s2 = g_ssrc[j + 2], s3 = g_ssrc[j + 3];
        float e0 = g_as[s0] + adi, e1 = g_as[s1] + adi,
              e2 = g_as[s2] + adi, e3 = g_as[s3] + adi;
        uint2 p0 = hh[s0 * 32 + lane], p1 = hh[s1 * 32 + lane],
              p2 = hh[s2 * 32 + lane], p3 = hh[s3 * 32 + lane];
        float x0 = __expf(leaky(e0) - m), x1 = __expf(leaky(e1) - m),
              x2 = __expf(leaky(e2) - m), x3 = __expf(leaky(e3) - m);
        denom += (x0 + x1) + (x2 + x3);
        float4 h0 = unpack_half4(p0), h1 = unpack_half4(p1),
               h2 = unpack_half4(p2), h3 = unpack_half4(p3);
        acc.x += x0 * h0.x + x1 * h1.x + x2 * h2.x + x3 * h3.x;
        acc.y += x0 * h0.y + x1 * h1.y + x2 * h2.y + x3 * h3.y;
        acc.z += x0 * h0.z + x1 * h1.z + x2 * h2.z + x3 * h3.z;
        acc.w += x0 * h0.w + x1 * h1.w + x2 * h2.w + x3 * h3.w;
    }
    for (; j < end; ++j) {
        int s = g_ssrc[j];
        float ex = __expf(leaky(g_as[s] + adi) - m);
        denom += ex;
        float4 hv = unpack_half4(hh[s * 32 + lane]);
        acc.x += ex * hv.x; acc.y += ex * hv.y;
        acc.z += ex * hv.z; acc.w += ex * hv.w;
    }
    float inv = 1.f / (denom + 1e-16f);
    float4 bv = ((const float4*)b)[lane];
    float4 r;
    r.x = fmaxf(acc.x * inv + bv.x, 0.f); r.y = fmaxf(acc.y * inv + bv.y, 0.f);
    r.z = fmaxf(acc.z * inv + bv.z, 0.f); r.w = fmaxf(acc.w * inv + bv.w, 0.f);
    // fused layer-3 projection: hc[c] = sum_k r[k] * W3[k][c], warp-reduced
    int k0 = lane * 4;
    float hc[OUTD];
#pragma unroll
    for (int c = 0; c < OUTD; ++c) {
        float s = r.x * Ws[(k0 + 0) * OUTD + c] + r.y * Ws[(k0 + 1) * OUTD + c]
                + r.z * Ws[(k0 + 2) * OUTD + c] + r.w * Ws[(k0 + 3) * OUTD + c];
#pragma unroll
        for (int o = 16; o; o >>= 1) s += __shfl_xor_sync(0xffffffffu, s, o);
        hc[c] = s;
    }
    if (lane == 0) {
        float s1 = 0.f, s2 = 0.f;
#pragma unroll
        for (int c = 0; c < OUTD; ++c) {
            g_h5[i * OUTD + c] = hc[c];
            s1 += hc[c] * As[c];
            s2 += hc[c] * Ad[c];
        }
        g_as[i] = s1; g_ad[i] = s2;
        atomicMax(&g_max2[blockIdx.x & 31], enc_f(s1));   // spread-slot, no barrier
    }
}

// ---------------- fused aggregation F=5 + bias + log_softmax (warp per node) -------
__global__ void k_agg5(const float* __restrict__ b3, float* __restrict__ out) {
    int warp = threadIdx.x >> 5, lane = threadIdx.x & 31;
    int i = blockIdx.x * 8 + warp;        // exact grid
    // reconstruct global layer-3 max from 32 spread slots
    float gm = dec_f(g_max2[lane]);
#pragma unroll
    for (int o = 16; o; o >>= 1) gm = fmaxf(gm, __shfl_xor_sync(0xffffffffu, gm, o));
    int start = g_off[i], end = g_off[i + 1];
    float adi = g_ad[i];
    float m = leaky(gm + adi);
    float a0 = 0.f, a1 = 0.f, a2 = 0.f, a3 = 0.f, a4 = 0.f, denom = 0.f;
    for (int j = start + lane; j < end; j += 32) {
        int s = g_ssrc[j];
        float ex = __expf(leaky(g_as[s] + adi) - m);
        denom += ex;
        const float* hp = &g_h5[s * OUTD];
        a0 += ex * hp[0]; a1 += ex * hp[1]; a2 += ex * hp[2];
        a3 += ex * hp[3]; a4 += ex * hp[4];
    }
#pragma unroll
    for (int o = 16; o; o >>= 1) {
        denom += __shfl_xor_sync(0xffffffffu, denom, o);
        a0 += __shfl_xor_sync(0xffffffffu, a0, o);
        a1 += __shfl_xor_sync(0xffffffffu, a1, o);
        a2 += __shfl_xor_sync(0xffffffffu, a2, o);
        a3 += __shfl_xor_sync(0xffffffffu, a3, o);
        a4 += __shfl_xor_sync(0xffffffffu, a4, o);
    }
    if (lane == 0) {
        float inv = 1.f / (denom + 1e-16f);
        float v[OUTD] = {a0 * inv + b3[0], a1 * inv + b3[1], a2 * inv + b3[2],
                         a3 * inv + b3[3], a4 * inv + b3[4]};
        float mx = -1e30f;
#pragma unroll
        for (int c = 0; c < OUTD; ++c) mx = fmaxf(mx, v[c]);
        float se = 0.f;
#pragma unroll
        for (int c = 0; c < OUTD; ++c) se += __expf(v[c] - mx);
        float lse = mx + logf(se);
#pragma unroll
        for (int c = 0; c < OUTD; ++c) out[i * OUTD + c] = v[c] - lse;
    }
}

// ---------------- launch ----------------
extern "C" void kernel_launch(void* const* d_in, const int* in_sizes, int n_in,
                              void* d_out, int out_size) {
    const float* x   = (const float*)d_in[0];
    const int*   ei  = (const int*)d_in[1];       // int32: JAX x64 is disabled
    const float* W1  = (const float*)d_in[2];
    const float* as1 = (const float*)d_in[3];
    const float* ad1 = (const float*)d_in[4];
    const float* b1  = (const float*)d_in[5];
    const float* W2  = (const float*)d_in[6];
    const float* as2 = (const float*)d_in[7];
    const float* ad2 = (const float*)d_in[8];
    const float* b2  = (const float*)d_in[9];
    const float* W3  = (const float*)d_in[10];
    const float* as3 = (const float*)d_in[11];
    const float* ad3 = (const float*)d_in[12];
    const float* b3  = (const float*)d_in[13];
    float* out = (float*)d_out;

    // CSR build (rebuilt every call — no caching)
    k_init<<<(N_NODES + 255) / 256, 256>>>(W2);
    k_hist<<<(N_EDGES / 4 + 255) / 256, 256>>>(ei);
    k_offsets<<<NBLK, SCAN_BS>>>();
    k_fill<<<(N_EDGES / 4 + 255) / 256, 256>>>(ei);

    int nwb = N_NODES / 8;   // 6250, exact — warp-per-node grids

    // layer 1
    k_gemm1<<<nwb, 256>>>(x, W1, as1, ad1);
    k_agg128<<<nwb, 256>>>(b1);
    // layer 2 (rowdot fused into GEMM epilogue)
    k_gemm2_wmma<<<(N_NODES + 63) / 64, 256>>>(as2, ad2);
    // layer-2 aggregation with fused layer-3 GEMM + dots (barrier-free max)
    k_agg128_fin<<<nwb, 256>>>(b2, W3, as3, ad3);
    // layer 3 softmax-aggregate + log_softmax
    k_agg5<<<nwb, 256>>>(b3, out);
}